// round 15
// baseline (speedup 1.0000x reference)
#include <cuda_runtime.h>
#include <cuda_bf16.h>
#include <cstdint>

#define NUM_NODE 8192
#define N_PTS_MAX 20000
#define FEAT_DIM 32
#define TILE 128
#define NTILE (NUM_NODE / TILE)   // 64 -> grid 64x64
#define WPAD 20                   // banks 20g+tq: perfect permutation, conflict-free

#define POS_R2 (0.0375f * 0.0375f)
#define NEG_R2 (0.1f * 0.1f)
#define EPSV 1e-7f
#define BIG2 1e10f
// s = p_i.p_j - 0.5|p_i|^2 - 0.5|p_j|^2 (= -d2/2); masks vs folded constants
#define CPOS (-0.5f * (POS_R2 - EPSV))    // pos mask: s > CPOS
#define CNEG (-0.5f * (NEG_R2 - EPSV))    // neg-mask FAILS: s >= CNEG

typedef unsigned long long ull;

#define FMA2(d, a, b, c) asm("fma.rn.f32x2 %0, %1, %2, %3;" : "=l"(d) : "l"(a), "l"(b), "l"(c))
#define ADD2(d, a, b)    asm("add.rn.f32x2 %0, %1, %2;"     : "=l"(d) : "l"(a), "l"(b))
#define PACK2(d, lo, hi) asm("mov.b64 %0, {%1, %2};" : "=l"(d) : "f"(lo), "f"(hi))
#define UNPACK2(lo, hi, s) asm("mov.b64 {%0, %1}, %2;" : "=f"(lo), "=f"(hi) : "l"(s))
#define SET_GT(r, a, b)  asm("set.gt.f32.f32 %0, %1, %2;" : "=f"(r) : "f"(a), "f"(b))
#define SET_GE(r, a, b)  asm("set.ge.f32.f32 %0, %1, %2;" : "=f"(r) : "f"(a), "f"(b))

// -------- scratch (allocation-free: __device__ globals) --------
__device__ uint32_t g_sfw[NUM_NODE * FEAT_DIM / 2];  // src feats bf16x2
__device__ uint32_t g_tfw[NUM_NODE * FEAT_DIM / 2];  // tgt feats bf16x2
__device__ float4   g_spA[NUM_NODE];      // src: (x, y, z, -0.5|p|^2) post-rot
__device__ float    g_sfn[NUM_NODE];      // src: |feat|^2 exact
__device__ float4   g_tc1[NUM_NODE];      // tgt dup: (x,x,y,y)
__device__ float4   g_tc2[NUM_NODE];      // tgt dup: (z,z, -0.5|p|^2, -0.5|p|^2)
__device__ float2   g_tfn2[NUM_NODE];     // tgt: (|feat|^2, |feat|^2)
__device__ int      g_rowmax[NUM_NODE];
__device__ int      g_rowmin[NUM_NODE];
__device__ unsigned g_ticket;

// ---------------- kernel 1: warp-per-node gather ----------------
__global__ void gather_kernel(const float* __restrict__ src_pcd,
                              const float* __restrict__ tgt_pcd,
                              const float* __restrict__ src_feats,
                              const float* __restrict__ tgt_feats,
                              const int* __restrict__ corr,
                              const float* __restrict__ rot,
                              const float* __restrict__ trans) {
    int node = (blockIdx.x * blockDim.x + threadIdx.x) >> 5;
    int lane = threadIdx.x & 31;
    if (node >= NUM_NODE) return;
    int ci = corr[2 * node + 0];
    int cj = corr[2 * node + 1];
    ci = min(max(ci, 0), N_PTS_MAX - 1);
    cj = min(max(cj, 0), N_PTS_MAX - 1);

    float fs = src_feats[ci * FEAT_DIM + lane];
    float ft = tgt_feats[cj * FEAT_DIM + lane];

    uint32_t sb = (uint32_t)__bfloat16_as_ushort(__float2bfloat16(fs));
    uint32_t tb = (uint32_t)__bfloat16_as_ushort(__float2bfloat16(ft));
    uint32_t snb = __shfl_down_sync(0xffffffffu, sb, 1);
    uint32_t tnb = __shfl_down_sync(0xffffffffu, tb, 1);
    if ((lane & 1) == 0) {
        g_sfw[node * (FEAT_DIM / 2) + (lane >> 1)] = sb | (snb << 16);
        g_tfw[node * (FEAT_DIM / 2) + (lane >> 1)] = tb | (tnb << 16);
    }

    float sn = fs * fs, tn = ft * ft;
#pragma unroll
    for (int off = 16; off > 0; off >>= 1) {
        sn += __shfl_xor_sync(0xffffffffu, sn, off);
        tn += __shfl_xor_sync(0xffffffffu, tn, off);
    }

    if (lane == 0) {
        float x = src_pcd[3 * ci + 0];
        float y = src_pcd[3 * ci + 1];
        float z = src_pcd[3 * ci + 2];
        float tx = rot[0] * x + rot[1] * y + rot[2] * z + trans[0];
        float ty = rot[3] * x + rot[4] * y + rot[5] * z + trans[1];
        float tz = rot[6] * x + rot[7] * y + rot[8] * z + trans[2];
        g_spA[node] = make_float4(tx, ty, tz, -0.5f * (tx * tx + ty * ty + tz * tz));
        g_sfn[node] = sn;

        float gx = tgt_pcd[3 * cj + 0];
        float gy = tgt_pcd[3 * cj + 1];
        float gz = tgt_pcd[3 * cj + 2];
        float pnT = -0.5f * (gx * gx + gy * gy + gz * gz);
        g_tc1[node] = make_float4(gx, gx, gy, gy);
        g_tc2[node] = make_float4(gz, gz, pnT, pnT);
        g_tfn2[node] = make_float2(tn, tn);

        g_rowmax[node] = 0;
        g_rowmin[node] = __float_as_int(BIG2);
        if (node == 0) g_ticket = 0;
    }
}

// ---------------- kernel 2: bf16 mma Gram + per-nf epilogue + fused tail loss ----------------
__global__ __launch_bounds__(128, 5) void mma_pair_kernel(float* __restrict__ out) {
    __shared__ uint32_t sAw[TILE * WPAD];      // 10 KB
    __shared__ uint32_t sBw[TILE * WPAD];      // 10 KB
    __shared__ ulonglong2 sC1[TILE];           // (x,x),(y,y)
    __shared__ ulonglong2 sC2[TILE];           // (z,z),(npn,npn)
    __shared__ ull       sC3[TILE];            // (fn,fn)
    __shared__ unsigned  s_last;

    const int t  = threadIdx.x;
    const int w  = t >> 5;
    const int l  = t & 31;
    const int g  = l >> 2;
    const int tq = l & 3;
    const int i0 = blockIdx.y * TILE;
    const int j0 = blockIdx.x * TILE;

    // ---- stage ----
    {
        const uint32_t* gA = &g_sfw[i0 * (FEAT_DIM / 2)];
        const uint32_t* gB = &g_tfw[j0 * (FEAT_DIM / 2)];
#pragma unroll
        for (int v = t; v < TILE * 16; v += 128) {
            int row = v >> 4, c = v & 15;
            sAw[row * WPAD + c] = gA[v];
            sBw[row * WPAD + c] = gB[v];
        }
        const ulonglong2* pc1 = reinterpret_cast<const ulonglong2*>(&g_tc1[j0]);
        const ulonglong2* pc2 = reinterpret_cast<const ulonglong2*>(&g_tc2[j0]);
        const ull* fn = reinterpret_cast<const ull*>(&g_tfn2[j0]);
        for (int v = t; v < TILE; v += 128) {
            sC1[v] = pc1[v];
            sC2[v] = pc2[v];
            sC3[v] = fn[v];
        }
    }
    __syncthreads();

    // ---- a-fragments for all K, both m-frags ----
    const int rbase = w * 32;
    uint32_t a[2][2][4];    // [ks][mf][frag]
#pragma unroll
    for (int ks = 0; ks < 2; ks++) {
        const int kw = ks * 8;
#pragma unroll
        for (int mf = 0; mf < 2; mf++) {
            int r0 = rbase + mf * 16 + g;
            a[ks][mf][0] = sAw[r0 * WPAD + kw + tq];
            a[ks][mf][1] = sAw[(r0 + 8) * WPAD + kw + tq];
            a[ks][mf][2] = sAw[r0 * WPAD + kw + tq + 4];
            a[ks][mf][3] = sAw[(r0 + 8) * WPAD + kw + tq + 4];
        }
    }

    // ---- packed row constants (epilogue) ----
    ull xi2[2], yi2[2], zi2[2], npn2[2], fn2[2];
#pragma unroll
    for (int mf = 0; mf < 2; mf++) {
        int rA = i0 + rbase + mf * 16 + g;
        float4 a4 = g_spA[rA];
        float4 b4 = g_spA[rA + 8];
        PACK2(xi2[mf], a4.x, b4.x);
        PACK2(yi2[mf], a4.y, b4.y);
        PACK2(zi2[mf], a4.z, b4.z);
        PACK2(npn2[mf], a4.w, b4.w);
        PACK2(fn2[mf], g_sfn[rA], g_sfn[rA + 8]);
    }
    ull m2; PACK2(m2, -2.f, -2.f);

    float mp[4] = {0.f, 0.f, 0.f, 0.f};
    float mn[4] = {BIG2, BIG2, BIG2, BIG2};

    // ---- per-nf: 4 MMAs then immediate epilogue (acc live range = 1 nf) ----
#pragma unroll
    for (int nf = 0; nf < 16; nf++) {
        const int jr = nf * 8 + g;
        float acc[2][4] = {{0.f, 0.f, 0.f, 0.f}, {0.f, 0.f, 0.f, 0.f}};
#pragma unroll
        for (int ks = 0; ks < 2; ks++) {
            const int kw = ks * 8;
            uint32_t b0 = sBw[jr * WPAD + kw + tq];
            uint32_t b1 = sBw[jr * WPAD + kw + tq + 4];
#pragma unroll
            for (int mf = 0; mf < 2; mf++) {
                asm volatile(
                    "mma.sync.aligned.m16n8k16.row.col.f32.bf16.bf16.f32 "
                    "{%0,%1,%2,%3}, {%4,%5,%6,%7}, {%8,%9}, {%0,%1,%2,%3};"
                    : "+f"(acc[mf][0]), "+f"(acc[mf][1]),
                      "+f"(acc[mf][2]), "+f"(acc[mf][3])
                    : "r"(a[ks][mf][0]), "r"(a[ks][mf][1]),
                      "r"(a[ks][mf][2]), "r"(a[ks][mf][3]),
                      "r"(b0), "r"(b1));
            }
        }
#pragma unroll
        for (int sub = 0; sub < 2; sub++) {
            int col = nf * 8 + tq * 2 + sub;
            ulonglong2 c1 = sC1[col];
            ulonglong2 c2 = sC2[col];
            ull tn2 = sC3[col];
#pragma unroll
            for (int mf = 0; mf < 2; mf++) {
                ull cc, s2, sntn2, G2, d2f2;
                ADD2(cc, c2.y, npn2[mf]);
                FMA2(s2, xi2[mf], c1.x, cc);
                FMA2(s2, yi2[mf], c1.y, s2);
                FMA2(s2, zi2[mf], c2.x, s2);        // s = dot - pni - pnj
                ADD2(sntn2, fn2[mf], tn2);
                PACK2(G2, acc[mf][sub], acc[mf][2 + sub]);
                FMA2(d2f2, m2, G2, sntn2);          // d2f = fn_i + fn_j - 2G
                float s0, s1, f0, f1;
                UNPACK2(s0, s1, s2);
                UNPACK2(f0, f1, d2f2);

                float rp0, rp1, rn0, rn1;
                SET_GT(rp0, s0, CPOS);
                SET_GT(rp1, s1, CPOS);
                SET_GE(rn0, s0, CNEG);
                SET_GE(rn1, s1, CNEG);
                mp[2 * mf]     = fmaxf(mp[2 * mf],     f0 * rp0);
                mp[2 * mf + 1] = fmaxf(mp[2 * mf + 1], f1 * rp1);
                mn[2 * mf]     = fminf(mn[2 * mf],     fmaf(rn0, BIG2, f0));
                mn[2 * mf + 1] = fminf(mn[2 * mf + 1], fmaf(rn1, BIG2, f1));
            }
        }
    }

    // quad-reduce then deterministic int atomics (all values clamped >= 0)
#pragma unroll
    for (int q = 0; q < 4; q++) {
        mp[q] = fmaxf(mp[q], __shfl_xor_sync(0xffffffffu, mp[q], 1));
        mp[q] = fmaxf(mp[q], __shfl_xor_sync(0xffffffffu, mp[q], 2));
        mn[q] = fminf(mn[q], __shfl_xor_sync(0xffffffffu, mn[q], 1));
        mn[q] = fminf(mn[q], __shfl_xor_sync(0xffffffffu, mn[q], 2));
    }
    if (tq == 0) {
#pragma unroll
        for (int q = 0; q < 4; q++) {
            int mf = q >> 1;
            int row = i0 + rbase + mf * 16 + g + (q & 1) * 8;
            atomicMax(&g_rowmax[row], __float_as_int(fmaxf(mp[q], 0.f)));
            atomicMin(&g_rowmin[row], __float_as_int(fmaxf(mn[q], 0.f)));
        }
    }

    // ---- fused final loss: last CTA reduces all rows (deterministic) ----
    __threadfence();
    __syncthreads();
    if (t == 0) {
        unsigned tk = atomicAdd(&g_ticket, 1u);
        s_last = (tk == (unsigned)(NTILE * NTILE - 1)) ? 1u : 0u;
    }
    __syncthreads();
    if (s_last) {
        __threadfence();
        float* sred = reinterpret_cast<float*>(sAw);   // reuse smem
        float acc2 = 0.f;
        for (int r = t; r < NUM_NODE; r += 128) {
            float mpv = __int_as_float(g_rowmax[r]);
            float mnv = __int_as_float(g_rowmin[r]);
            acc2 += fmaxf(sqrtf(mpv + EPSV) - 0.1f, 0.f)
                  + fmaxf(1.4f - sqrtf(mnv + EPSV), 0.f);
        }
        sred[t] = acc2;
        __syncthreads();
#pragma unroll
        for (int off = 64; off > 0; off >>= 1) {
            if (t < off) sred[t] += sred[t + off];
            __syncthreads();
        }
        if (t == 0) out[0] = sred[0] / (float)NUM_NODE;
    }
}

extern "C" void kernel_launch(void* const* d_in, const int* in_sizes, int n_in,
                              void* d_out, int out_size) {
    const float* src_pcd  = (const float*)d_in[0];
    const float* tgt_pcd  = (const float*)d_in[1];
    const float* src_feats = (const float*)d_in[2];
    const float* tgt_feats = (const float*)d_in[3];
    const int* corr    = (const int*)d_in[4];
    const float* rot   = (const float*)d_in[5];
    const float* trans = (const float*)d_in[6];
    float* out = (float*)d_out;

    gather_kernel<<<NUM_NODE * 32 / 256, 256>>>(src_pcd, tgt_pcd, src_feats, tgt_feats,
                                                corr, rot, trans);
    dim3 grid(NTILE, NTILE);
    mma_pair_kernel<<<grid, 128>>>(out);
}

// round 16
// speedup vs baseline: 1.3483x; 1.3483x over previous
#include <cuda_runtime.h>
#include <cuda_bf16.h>
#include <cstdint>

#define NUM_NODE 8192
#define N_PTS_MAX 20000
#define FEAT_DIM 32
#define TILE 128
#define NTILE (NUM_NODE / TILE)   // 64 -> grid 64x64
#define WPAD 20                   // banks 20g+tq: perfect permutation, conflict-free

#define POS_R2 (0.0375f * 0.0375f)
#define NEG_R2 (0.1f * 0.1f)
#define EPSV 1e-7f
#define BIG2 1e10f
// s = p_i.p_j - 0.5|p_i|^2 - 0.5|p_j|^2 (= -d2/2); masks vs folded constants
#define CPOS (-0.5f * (POS_R2 - EPSV))    // pos mask: s > CPOS
#define CNEG (-0.5f * (NEG_R2 - EPSV))    // neg-mask FAILS: s >= CNEG

typedef unsigned long long ull;

#define FMA2(d, a, b, c) asm("fma.rn.f32x2 %0, %1, %2, %3;" : "=l"(d) : "l"(a), "l"(b), "l"(c))
#define ADD2(d, a, b)    asm("add.rn.f32x2 %0, %1, %2;"     : "=l"(d) : "l"(a), "l"(b))
#define PACK2(d, lo, hi) asm("mov.b64 %0, {%1, %2};" : "=l"(d) : "f"(lo), "f"(hi))
#define UNPACK2(lo, hi, s) asm("mov.b64 {%0, %1}, %2;" : "=f"(lo), "=f"(hi) : "l"(s))
#define SET_GT(r, a, b)  asm("set.gt.f32.f32 %0, %1, %2;" : "=f"(r) : "f"(a), "f"(b))
#define SET_GE(r, a, b)  asm("set.ge.f32.f32 %0, %1, %2;" : "=f"(r) : "f"(a), "f"(b))

// -------- scratch (allocation-free: __device__ globals) --------
__device__ uint32_t g_sfw[NUM_NODE * FEAT_DIM / 2];  // src feats bf16x2
__device__ uint32_t g_tfw[NUM_NODE * FEAT_DIM / 2];  // tgt feats bf16x2
__device__ float4   g_spA[NUM_NODE];      // src: (x, y, z, -0.5|p|^2) post-rot
__device__ float    g_sfn[NUM_NODE];      // src: |feat|^2 exact
__device__ float4   g_tc1[NUM_NODE];      // tgt dup: (x,x,y,y)
__device__ float4   g_tc2[NUM_NODE];      // tgt dup: (z,z, -0.5|p|^2, -0.5|p|^2)
__device__ float2   g_tfn2[NUM_NODE];     // tgt: (|feat|^2, |feat|^2)
__device__ int      g_rowmax[NUM_NODE];
__device__ int      g_rowmin[NUM_NODE];

__device__ __forceinline__ uint32_t bf16b(float x) {
    return (uint32_t)__bfloat16_as_ushort(__float2bfloat16(x));
}

// ---------------- kernel 1: gather, 4 nodes/warp, 8 lanes/node ----------------
__global__ void gather_kernel(const float* __restrict__ src_pcd,
                              const float* __restrict__ tgt_pcd,
                              const float* __restrict__ src_feats,
                              const float* __restrict__ tgt_feats,
                              const int* __restrict__ corr,
                              const float* __restrict__ rot,
                              const float* __restrict__ trans) {
    const int warp = (blockIdx.x * blockDim.x + threadIdx.x) >> 5;
    const int lane = threadIdx.x & 31;
    const int sub  = lane & 7;               // 8 lanes per node
    const int node = warp * 4 + (lane >> 3); // 4 nodes per warp
    if (node >= NUM_NODE) return;

    int ci = corr[2 * node + 0];
    int cj = corr[2 * node + 1];
    ci = min(max(ci, 0), N_PTS_MAX - 1);
    cj = min(max(cj, 0), N_PTS_MAX - 1);

    const float4* sf4 = reinterpret_cast<const float4*>(src_feats);
    const float4* tf4 = reinterpret_cast<const float4*>(tgt_feats);
    float4 fs = sf4[ci * 8 + sub];
    float4 ft = tf4[cj * 8 + sub];

    // norms from exact fp32 values
    float sn = fmaf(fs.x, fs.x, fmaf(fs.y, fs.y, fmaf(fs.z, fs.z, fs.w * fs.w)));
    float tn = fmaf(ft.x, ft.x, fmaf(ft.y, ft.y, fmaf(ft.z, ft.z, ft.w * ft.w)));
#pragma unroll
    for (int off = 4; off > 0; off >>= 1) {
        sn += __shfl_xor_sync(0xffffffffu, sn, off, 8);
        tn += __shfl_xor_sync(0xffffffffu, tn, off, 8);
    }

    // bf16 pack (adjacent-k pairs) directly from the float4 — no shuffles
    uint2 sw = make_uint2(bf16b(fs.x) | (bf16b(fs.y) << 16),
                          bf16b(fs.z) | (bf16b(fs.w) << 16));
    uint2 tw = make_uint2(bf16b(ft.x) | (bf16b(ft.y) << 16),
                          bf16b(ft.z) | (bf16b(ft.w) << 16));
    reinterpret_cast<uint2*>(g_sfw)[node * 8 + sub] = sw;
    reinterpret_cast<uint2*>(g_tfw)[node * 8 + sub] = tw;

    if (sub == 0) {
        float x = src_pcd[3 * ci + 0];
        float y = src_pcd[3 * ci + 1];
        float z = src_pcd[3 * ci + 2];
        float tx = rot[0] * x + rot[1] * y + rot[2] * z + trans[0];
        float ty = rot[3] * x + rot[4] * y + rot[5] * z + trans[1];
        float tz = rot[6] * x + rot[7] * y + rot[8] * z + trans[2];
        g_spA[node] = make_float4(tx, ty, tz, -0.5f * (tx * tx + ty * ty + tz * tz));
        g_sfn[node] = sn;

        float gx = tgt_pcd[3 * cj + 0];
        float gy = tgt_pcd[3 * cj + 1];
        float gz = tgt_pcd[3 * cj + 2];
        float pnT = -0.5f * (gx * gx + gy * gy + gz * gz);
        g_tc1[node] = make_float4(gx, gx, gy, gy);
        g_tc2[node] = make_float4(gz, gz, pnT, pnT);
        g_tfn2[node] = make_float2(tn, tn);

        g_rowmax[node] = 0;
        g_rowmin[node] = __float_as_int(BIG2);
    }
}

// ---------------- kernel 2: bf16 mma Gram + per-nf epilogue (R11, unchanged) ----------------
__global__ __launch_bounds__(128, 5) void mma_pair_kernel() {
    __shared__ uint32_t sAw[TILE * WPAD];      // 10 KB
    __shared__ uint32_t sBw[TILE * WPAD];      // 10 KB
    __shared__ ulonglong2 sC1[TILE];           // (x,x),(y,y)
    __shared__ ulonglong2 sC2[TILE];           // (z,z),(npn,npn)
    __shared__ ull       sC3[TILE];            // (fn,fn)

    const int t  = threadIdx.x;
    const int w  = t >> 5;
    const int l  = t & 31;
    const int g  = l >> 2;
    const int tq = l & 3;
    const int i0 = blockIdx.y * TILE;
    const int j0 = blockIdx.x * TILE;

    // ---- stage ----
    {
        const uint32_t* gA = &g_sfw[i0 * (FEAT_DIM / 2)];
        const uint32_t* gB = &g_tfw[j0 * (FEAT_DIM / 2)];
#pragma unroll
        for (int v = t; v < TILE * 16; v += 128) {
            int row = v >> 4, c = v & 15;
            sAw[row * WPAD + c] = gA[v];
            sBw[row * WPAD + c] = gB[v];
        }
        const ulonglong2* pc1 = reinterpret_cast<const ulonglong2*>(&g_tc1[j0]);
        const ulonglong2* pc2 = reinterpret_cast<const ulonglong2*>(&g_tc2[j0]);
        const ull* fn = reinterpret_cast<const ull*>(&g_tfn2[j0]);
        for (int v = t; v < TILE; v += 128) {
            sC1[v] = pc1[v];
            sC2[v] = pc2[v];
            sC3[v] = fn[v];
        }
    }
    __syncthreads();

    // ---- a-fragments for all K, both m-frags ----
    const int rbase = w * 32;
    uint32_t a[2][2][4];    // [ks][mf][frag]
#pragma unroll
    for (int ks = 0; ks < 2; ks++) {
        const int kw = ks * 8;
#pragma unroll
        for (int mf = 0; mf < 2; mf++) {
            int r0 = rbase + mf * 16 + g;
            a[ks][mf][0] = sAw[r0 * WPAD + kw + tq];
            a[ks][mf][1] = sAw[(r0 + 8) * WPAD + kw + tq];
            a[ks][mf][2] = sAw[r0 * WPAD + kw + tq + 4];
            a[ks][mf][3] = sAw[(r0 + 8) * WPAD + kw + tq + 4];
        }
    }

    // ---- packed row constants (epilogue) ----
    ull xi2[2], yi2[2], zi2[2], npn2[2], fn2[2];
#pragma unroll
    for (int mf = 0; mf < 2; mf++) {
        int rA = i0 + rbase + mf * 16 + g;
        float4 a4 = g_spA[rA];
        float4 b4 = g_spA[rA + 8];
        PACK2(xi2[mf], a4.x, b4.x);
        PACK2(yi2[mf], a4.y, b4.y);
        PACK2(zi2[mf], a4.z, b4.z);
        PACK2(npn2[mf], a4.w, b4.w);
        PACK2(fn2[mf], g_sfn[rA], g_sfn[rA + 8]);
    }
    ull m2; PACK2(m2, -2.f, -2.f);

    float mp[4] = {0.f, 0.f, 0.f, 0.f};
    float mn[4] = {BIG2, BIG2, BIG2, BIG2};

    // ---- per-nf: 4 MMAs then immediate epilogue (acc live range = 1 nf) ----
#pragma unroll
    for (int nf = 0; nf < 16; nf++) {
        const int jr = nf * 8 + g;
        float acc[2][4] = {{0.f, 0.f, 0.f, 0.f}, {0.f, 0.f, 0.f, 0.f}};
#pragma unroll
        for (int ks = 0; ks < 2; ks++) {
            const int kw = ks * 8;
            uint32_t b0 = sBw[jr * WPAD + kw + tq];
            uint32_t b1 = sBw[jr * WPAD + kw + tq + 4];
#pragma unroll
            for (int mf = 0; mf < 2; mf++) {
                asm volatile(
                    "mma.sync.aligned.m16n8k16.row.col.f32.bf16.bf16.f32 "
                    "{%0,%1,%2,%3}, {%4,%5,%6,%7}, {%8,%9}, {%0,%1,%2,%3};"
                    : "+f"(acc[mf][0]), "+f"(acc[mf][1]),
                      "+f"(acc[mf][2]), "+f"(acc[mf][3])
                    : "r"(a[ks][mf][0]), "r"(a[ks][mf][1]),
                      "r"(a[ks][mf][2]), "r"(a[ks][mf][3]),
                      "r"(b0), "r"(b1));
            }
        }
#pragma unroll
        for (int sub = 0; sub < 2; sub++) {
            int col = nf * 8 + tq * 2 + sub;
            ulonglong2 c1 = sC1[col];
            ulonglong2 c2 = sC2[col];
            ull tn2 = sC3[col];
#pragma unroll
            for (int mf = 0; mf < 2; mf++) {
                ull cc, s2, sntn2, G2, d2f2;
                ADD2(cc, c2.y, npn2[mf]);
                FMA2(s2, xi2[mf], c1.x, cc);
                FMA2(s2, yi2[mf], c1.y, s2);
                FMA2(s2, zi2[mf], c2.x, s2);        // s = dot - pni - pnj
                ADD2(sntn2, fn2[mf], tn2);
                PACK2(G2, acc[mf][sub], acc[mf][2 + sub]);
                FMA2(d2f2, m2, G2, sntn2);          // d2f = fn_i + fn_j - 2G
                float s0, s1, f0, f1;
                UNPACK2(s0, s1, s2);
                UNPACK2(f0, f1, d2f2);

                float rp0, rp1, rn0, rn1;
                SET_GT(rp0, s0, CPOS);
                SET_GT(rp1, s1, CPOS);
                SET_GE(rn0, s0, CNEG);
                SET_GE(rn1, s1, CNEG);
                mp[2 * mf]     = fmaxf(mp[2 * mf],     f0 * rp0);
                mp[2 * mf + 1] = fmaxf(mp[2 * mf + 1], f1 * rp1);
                mn[2 * mf]     = fminf(mn[2 * mf],     fmaf(rn0, BIG2, f0));
                mn[2 * mf + 1] = fminf(mn[2 * mf + 1], fmaf(rn1, BIG2, f1));
            }
        }
    }

    // quad-reduce then deterministic int atomics (all values clamped >= 0)
#pragma unroll
    for (int q = 0; q < 4; q++) {
        mp[q] = fmaxf(mp[q], __shfl_xor_sync(0xffffffffu, mp[q], 1));
        mp[q] = fmaxf(mp[q], __shfl_xor_sync(0xffffffffu, mp[q], 2));
        mn[q] = fminf(mn[q], __shfl_xor_sync(0xffffffffu, mn[q], 1));
        mn[q] = fminf(mn[q], __shfl_xor_sync(0xffffffffu, mn[q], 2));
    }
    if (tq == 0) {
#pragma unroll
        for (int q = 0; q < 4; q++) {
            int mf = q >> 1;
            int row = i0 + rbase + mf * 16 + g + (q & 1) * 8;
            atomicMax(&g_rowmax[row], __float_as_int(fmaxf(mp[q], 0.f)));
            atomicMin(&g_rowmin[row], __float_as_int(fmaxf(mn[q], 0.f)));
        }
    }
}

// ---------------- kernel 3: final loss (shuffle-based reduce) ----------------
__global__ __launch_bounds__(1024) void loss_kernel(float* __restrict__ out) {
    __shared__ float spart[32];
    const int t = threadIdx.x;
    float acc = 0.f;
#pragma unroll
    for (int k = 0; k < NUM_NODE / 1024; k++) {
        int r = t + k * 1024;
        float mpv = __int_as_float(g_rowmax[r]);
        float mnv = __int_as_float(g_rowmin[r]);
        acc += fmaxf(sqrtf(mpv + EPSV) - 0.1f, 0.f)
             + fmaxf(1.4f - sqrtf(mnv + EPSV), 0.f);
    }
#pragma unroll
    for (int off = 16; off > 0; off >>= 1)
        acc += __shfl_xor_sync(0xffffffffu, acc, off);
    if ((t & 31) == 0) spart[t >> 5] = acc;
    __syncthreads();
    if (t < 32) {
        float v = spart[t];
#pragma unroll
        for (int off = 16; off > 0; off >>= 1)
            v += __shfl_xor_sync(0xffffffffu, v, off);
        if (t == 0) out[0] = v / (float)NUM_NODE;
    }
}

extern "C" void kernel_launch(void* const* d_in, const int* in_sizes, int n_in,
                              void* d_out, int out_size) {
    const float* src_pcd  = (const float*)d_in[0];
    const float* tgt_pcd  = (const float*)d_in[1];
    const float* src_feats = (const float*)d_in[2];
    const float* tgt_feats = (const float*)d_in[3];
    const int* corr    = (const int*)d_in[4];
    const float* rot   = (const float*)d_in[5];
    const float* trans = (const float*)d_in[6];
    float* out = (float*)d_out;

    // 4 nodes per warp -> 2048 warps -> 256 blocks of 256
    gather_kernel<<<NUM_NODE * 8 / 256, 256>>>(src_pcd, tgt_pcd, src_feats, tgt_feats,
                                               corr, rot, trans);
    dim3 grid(NTILE, NTILE);
    mma_pair_kernel<<<grid, 128>>>();
    loss_kernel<<<1, 1024>>>(out);
}